// round 16
// baseline (speedup 1.0000x reference)
#include <cuda_runtime.h>
#include <cuda_fp16.h>
#include <math.h>
#include <stdint.h>

#define N_NODES 100000
#define N_EDGES 1600000
#define SCAN_B 512
#define NB ((N_NODES + SCAN_B - 1) / SCAN_B)   // 196
#define GEMM_BLOCKS ((N_NODES + 63) / 64)      // 1563

// ---------------- scratch (device globals; no allocation allowed) ----------
__device__ float  g_agg1[(size_t)N_NODES * 64];
__device__ float  g_h   [(size_t)N_NODES * 128];
__device__ __half g_xh  [(size_t)N_NODES * 64];   // fp16 copy of x
__device__ __half g_th  [(size_t)N_NODES * 64];   // fp16 t = h @ W_l2
__device__ int    g_cnt [N_NODES];                // zero at entry (restored by agg2)
__device__ int    g_off [N_NODES];
__device__ int    g_pos [N_NODES];
__device__ int    g_adj [N_EDGES];
__device__ int    g_blocksum[NB];
__device__ int    g_blockoff[NB];

// ---------------- K1: x->fp16 conversion + degree count ----------------------
__global__ void k1_kernel(const float* __restrict__ x, const int* __restrict__ dst,
                          __half* __restrict__ xh) {
    int gid = blockIdx.x * 256 + threadIdx.x;    // exactly 1.6M threads
    // convert: 1.6M float4 == 6.4M floats == all of x
    float4 v = __ldg((const float4*)x + gid);
    ((__half2*)xh)[2 * gid]     = __floats2half2_rn(v.x, v.y);
    ((__half2*)xh)[2 * gid + 1] = __floats2half2_rn(v.z, v.w);
    // count (same bound: N_EDGES == 1.6M)
    atomicAdd(&g_cnt[__ldg(&dst[gid])], 1);
}

// ---------------- 3-kernel scan (R13-proven) ----------------------------------
__global__ void reduce_kernel() {
    __shared__ int s[SCAN_B / 32];
    int i = blockIdx.x * SCAN_B + threadIdx.x;
    int v = (i < N_NODES) ? g_cnt[i] : 0;
#pragma unroll
    for (int o = 16; o > 0; o >>= 1) v += __shfl_down_sync(0xffffffffu, v, o);
    if ((threadIdx.x & 31) == 0) s[threadIdx.x >> 5] = v;
    __syncthreads();
    if (threadIdx.x == 0) {
        int t = 0;
#pragma unroll
        for (int w = 0; w < SCAN_B / 32; w++) t += s[w];
        g_blocksum[blockIdx.x] = t;
    }
}

__global__ void scanblock_kernel() {
    __shared__ int s[256];
    int v = (threadIdx.x < NB) ? g_blocksum[threadIdx.x] : 0;
    s[threadIdx.x] = v;
    __syncthreads();
    for (int d = 1; d < 256; d <<= 1) {
        int t = (threadIdx.x >= d) ? s[threadIdx.x - d] : 0;
        __syncthreads();
        s[threadIdx.x] += t;
        __syncthreads();
    }
    if (threadIdx.x < NB)
        g_blockoff[threadIdx.x] = (threadIdx.x == 0) ? 0 : s[threadIdx.x - 1];
}

__global__ void scatteroff_kernel() {
    __shared__ int s[SCAN_B];
    int b = blockIdx.x;
    int i = b * SCAN_B + threadIdx.x;
    int v = (i < N_NODES) ? g_cnt[i] : 0;
    s[threadIdx.x] = v;
    __syncthreads();
    for (int d = 1; d < SCAN_B; d <<= 1) {
        int t = (threadIdx.x >= d) ? s[threadIdx.x - d] : 0;
        __syncthreads();
        s[threadIdx.x] += t;
        __syncthreads();
    }
    if (i < N_NODES) {
        int excl = s[threadIdx.x] - v + g_blockoff[b];
        g_off[i] = excl;
        g_pos[i] = excl;
    }
}

__global__ void fill_kernel(const int* __restrict__ src, const int* __restrict__ dst) {
    int e = blockIdx.x * blockDim.x + threadIdx.x;
    if (e < N_EDGES) {
        int d = dst[e];
        int p = atomicAdd(&g_pos[d], 1);
        g_adj[p] = src[e];
    }
}

// ---------------- pull aggregation over fp16 features ------------------------
// FIN=1 fuses layer-2 epilogue: out = sigmoid(mean + r2), and re-zeroes g_cnt.
template <int FIN>
__global__ void __launch_bounds__(256)
agg16_kernel(const __half* __restrict__ feat, float* __restrict__ outp) {
    int node = blockIdx.x * 8 + (threadIdx.x >> 5);
    if (node >= N_NODES) return;
    int lane = threadIdx.x & 31;
    int half = lane >> 4;
    int q = lane & 15;
    int off = __ldg(&g_off[node]);
    int c = __ldg(&g_cnt[node]);
    if (FIN && lane == 0) g_cnt[node] = 0;   // restore invariant for next call
    const int* adj = g_adj + off;
    float4 acc = make_float4(0.f, 0.f, 0.f, 0.f);
    int i = half;
    for (; i + 6 < c; i += 8) {
        int s0 = __ldg(&adj[i]);
        int s1 = __ldg(&adj[i + 2]);
        int s2 = __ldg(&adj[i + 4]);
        int s3 = __ldg(&adj[i + 6]);
        uint2 r0 = __ldg((const uint2*)(feat + (size_t)s0 * 64) + q);
        uint2 r1 = __ldg((const uint2*)(feat + (size_t)s1 * 64) + q);
        uint2 r2 = __ldg((const uint2*)(feat + (size_t)s2 * 64) + q);
        uint2 r3 = __ldg((const uint2*)(feat + (size_t)s3 * 64) + q);
        float2 a0 = __half22float2(*(__half2*)&r0.x), b0 = __half22float2(*(__half2*)&r0.y);
        float2 a1 = __half22float2(*(__half2*)&r1.x), b1 = __half22float2(*(__half2*)&r1.y);
        float2 a2 = __half22float2(*(__half2*)&r2.x), b2 = __half22float2(*(__half2*)&r2.y);
        float2 a3 = __half22float2(*(__half2*)&r3.x), b3 = __half22float2(*(__half2*)&r3.y);
        acc.x += (a0.x + a1.x) + (a2.x + a3.x);
        acc.y += (a0.y + a1.y) + (a2.y + a3.y);
        acc.z += (b0.x + b1.x) + (b2.x + b3.x);
        acc.w += (b0.y + b1.y) + (b2.y + b3.y);
    }
    for (; i < c; i += 2) {
        int s0 = __ldg(&adj[i]);
        uint2 r0 = __ldg((const uint2*)(feat + (size_t)s0 * 64) + q);
        float2 a0 = __half22float2(*(__half2*)&r0.x), b0 = __half22float2(*(__half2*)&r0.y);
        acc.x += a0.x; acc.y += a0.y; acc.z += b0.x; acc.w += b0.y;
    }
    acc.x += __shfl_xor_sync(0xffffffffu, acc.x, 16);
    acc.y += __shfl_xor_sync(0xffffffffu, acc.y, 16);
    acc.z += __shfl_xor_sync(0xffffffffu, acc.z, 16);
    acc.w += __shfl_xor_sync(0xffffffffu, acc.w, 16);
    if (half == 0) {
        float sc = 1.0f / (float)max(c, 1);
        float4* dp = (float4*)(outp + (size_t)node * 64) + q;
        if (FIN) {
            float4 r = *dp;   // r2 written by gemm2
            float4 o;
            o.x = 1.0f / (1.0f + expf(-(acc.x * sc + r.x)));
            o.y = 1.0f / (1.0f + expf(-(acc.y * sc + r.y)));
            o.z = 1.0f / (1.0f + expf(-(acc.z * sc + r.z)));
            o.w = 1.0f / (1.0f + expf(-(acc.w * sc + r.w)));
            *dp = o;
        } else {
            *dp = make_float4(acc.x * sc, acc.y * sc, acc.z * sc, acc.w * sc);
        }
    }
}

// ---------------- bf16 split helpers ----------------------------------------
__device__ __forceinline__ uint32_t bf16hi_bits(float a) {
    uint32_t u = __float_as_uint(a);
    return (u + 0x7FFFu + ((u >> 16) & 1u)) & 0xFFFF0000u;  // RN-even to bf16
}
__device__ __forceinline__ void split_pack(float x0, float x1,
                                           uint32_t& hw, uint32_t& lw) {
    uint32_t r0 = bf16hi_bits(x0), r1 = bf16hi_bits(x1);
    hw = (r1 & 0xFFFF0000u) | (r0 >> 16);
    float l0 = x0 - __uint_as_float(r0);
    float l1 = x1 - __uint_as_float(r1);
    asm("cvt.rn.bf16x2.f32 %0, %1, %2;" : "=r"(lw) : "f"(l1), "f"(l0));
}

#define MMA_BF16(c, a0, a1, a2, a3, b0, b1) \
    asm volatile("mma.sync.aligned.m16n8k16.row.col.f32.bf16.bf16.f32 " \
        "{%0,%1,%2,%3}, {%4,%5,%6,%7}, {%8,%9}, {%0,%1,%2,%3};" \
        : "+f"((c)[0]), "+f"((c)[1]), "+f"((c)[2]), "+f"((c)[3]) \
        : "r"(a0), "r"(a1), "r"(a2), "r"(a3), "r"(b0), "r"(b1))

// ---------------- mma.sync bf16 3-term GEMM (R13-exact) ----------------------
// Tile: 64 rows x 128 cols, K=128. 256 threads = 8 warps (4 row x 2 col groups).
// MODE 1: h = relu([agg1 | x] @ [W_l1 ; W_r1] + b1)  -> outA [row][128] fp32
// MODE 2: A=h; cols 0-63:  t = h@W_l2 -> outH[row][64] fp16;
//               cols 64-127: r2 = h@W_r2 + b2 -> outB[row][64] fp32
#define A_STR 68
#define W_STR 136
#define SM_AH 0
#define SM_AL (SM_AH + 64 * A_STR)
#define SM_WH (SM_AL + 64 * A_STR)
#define SM_WL (SM_WH + 64 * W_STR)
#define SM_BIAS (SM_WL + 64 * W_STR)
#define SM_WORDS (SM_BIAS + 128)              // 26240 words = 104960 B

template <int MODE>
__global__ void __launch_bounds__(256, 2)
mma_gemm_kernel(const float* __restrict__ A0, const float* __restrict__ A1,
                const float* __restrict__ Wa, const float* __restrict__ Wb,
                const float* __restrict__ bias,
                float* __restrict__ outA, float* __restrict__ outB,
                __half* __restrict__ outH) {
    extern __shared__ uint32_t smw[];
    float* sB = (float*)(smw + SM_BIAS);
    const int tid = threadIdx.x;
    const int base = blockIdx.x * 64;

    if (tid < 128)
        sB[tid] = (MODE == 1) ? __ldg(&bias[tid])
                              : (tid < 64 ? 0.0f : __ldg(&bias[tid - 64]));

    // ---- stage A: 64 rows x 64 k-pairs, split hi/lo ----
#pragma unroll
    for (int i = 0; i < 16; i++) {
        int idx = tid + 256 * i;
        int row = idx >> 6, k2 = idx & 63;
        int grow = base + row;
        float2 v = make_float2(0.f, 0.f);
        if (grow < N_NODES) {
            if (MODE == 1)
                v = (k2 < 32)
                    ? __ldg((const float2*)(A0 + (size_t)grow * 64) + k2)
                    : __ldg((const float2*)(A1 + (size_t)grow * 64) + (k2 - 32));
            else
                v = __ldg((const float2*)(A0 + (size_t)grow * 128) + k2);
        }
        uint32_t hw, lw;
        split_pack(v.x, v.y, hw, lw);
        smw[SM_AH + row * A_STR + k2] = hw;
        smw[SM_AL + row * A_STR + k2] = lw;
    }

    // ---- stage W: 64 k-pairs x 128 cols, split hi/lo ----
#pragma unroll
    for (int i = 0; i < 32; i++) {
        int idx = tid + 256 * i;
        int k2 = idx >> 7, n = idx & 127;
        int k = 2 * k2;
        float w0, w1;
        if (MODE == 1) {
            if (k < 64) { w0 = __ldg(&Wa[k * 128 + n]); w1 = __ldg(&Wa[(k + 1) * 128 + n]); }
            else        { w0 = __ldg(&Wb[(k - 64) * 128 + n]); w1 = __ldg(&Wb[(k - 63) * 128 + n]); }
        } else {
            if (n < 64) { w0 = __ldg(&Wa[k * 64 + n]); w1 = __ldg(&Wa[(k + 1) * 64 + n]); }
            else        { w0 = __ldg(&Wb[k * 64 + n - 64]); w1 = __ldg(&Wb[(k + 1) * 64 + n - 64]); }
        }
        uint32_t hw, lw;
        split_pack(w0, w1, hw, lw);
        smw[SM_WH + k2 * W_STR + n] = hw;
        smw[SM_WL + k2 * W_STR + n] = lw;
    }
    __syncthreads();

    // ---- mma compute ----
    const int lane = tid & 31;
    const int g = lane >> 2, q = lane & 3;
    const int wid = tid >> 5;
    const int Rbase = (wid & 3) * 16;
    const int Cw = (wid >> 2) * 64;
    const int rA0 = SM_AH + (Rbase + g) * A_STR;
    const int rA1 = SM_AH + (Rbase + g + 8) * A_STR;
    const int lA0 = SM_AL + (Rbase + g) * A_STR;
    const int lA1 = SM_AL + (Rbase + g + 8) * A_STR;

    float acc[8][4];
#pragma unroll
    for (int nt = 0; nt < 8; nt++)
#pragma unroll
        for (int p = 0; p < 4; p++) acc[nt][p] = 0.0f;

#pragma unroll
    for (int ks = 0; ks < 8; ks++) {
        int aw = ks * 8;
        uint32_t ah0 = smw[rA0 + aw + q],     ah1 = smw[rA1 + aw + q];
        uint32_t ah2 = smw[rA0 + aw + q + 4], ah3 = smw[rA1 + aw + q + 4];
        uint32_t al0 = smw[lA0 + aw + q],     al1 = smw[lA1 + aw + q];
        uint32_t al2 = smw[lA0 + aw + q + 4], al3 = smw[lA1 + aw + q + 4];
        int wr0 = (aw + q) * W_STR, wr1 = (aw + q + 4) * W_STR;
#pragma unroll
        for (int nt = 0; nt < 8; nt++) {
            int n = Cw + nt * 8 + g;
            uint32_t bh0 = smw[SM_WH + wr0 + n], bh1 = smw[SM_WH + wr1 + n];
            uint32_t bl0 = smw[SM_WL + wr0 + n], bl1 = smw[SM_WL + wr1 + n];
            MMA_BF16(acc[nt], ah0, ah1, ah2, ah3, bh0, bh1);
            MMA_BF16(acc[nt], al0, al1, al2, al3, bh0, bh1);
            MMA_BF16(acc[nt], ah0, ah1, ah2, ah3, bl0, bl1);
        }
    }

    // ---- epilogue ----
    const int r0 = base + Rbase + g;
    const int r1 = r0 + 8;
#pragma unroll
    for (int nt = 0; nt < 8; nt++) {
        int col = Cw + nt * 8 + 2 * q;
        float v00 = acc[nt][0] + sB[col], v01 = acc[nt][1] + sB[col + 1];
        float v10 = acc[nt][2] + sB[col], v11 = acc[nt][3] + sB[col + 1];
        if (MODE == 1) {
            v00 = fmaxf(v00, 0.f); v01 = fmaxf(v01, 0.f);
            v10 = fmaxf(v10, 0.f); v11 = fmaxf(v11, 0.f);
            if (r0 < N_NODES)
                *(float2*)(outA + (size_t)r0 * 128 + col) = make_float2(v00, v01);
            if (r1 < N_NODES)
                *(float2*)(outA + (size_t)r1 * 128 + col) = make_float2(v10, v11);
        } else {
            if (Cw == 0) {   // t -> fp16
                if (r0 < N_NODES)
                    *(__half2*)(outH + (size_t)r0 * 64 + col) = __floats2half2_rn(v00, v01);
                if (r1 < N_NODES)
                    *(__half2*)(outH + (size_t)r1 * 64 + col) = __floats2half2_rn(v10, v11);
            } else {         // r2 + b2 -> out (fp32)
                int cc = col - 64;
                if (r0 < N_NODES)
                    *(float2*)(outB + (size_t)r0 * 64 + cc) = make_float2(v00, v01);
                if (r1 < N_NODES)
                    *(float2*)(outB + (size_t)r1 * 64 + cc) = make_float2(v10, v11);
            }
        }
    }
}

// ---------------- launch ------------------------------------------------------
extern "C" void kernel_launch(void* const* d_in, const int* in_sizes, int n_in,
                              void* d_out, int out_size) {
    const float* x    = (const float*)d_in[0];
    const int*   ei   = (const int*)d_in[1];
    const float* W_l1 = (const float*)d_in[2];
    const float* W_r1 = (const float*)d_in[3];
    const float* b1   = (const float*)d_in[4];
    const float* W_l2 = (const float*)d_in[5];
    const float* W_r2 = (const float*)d_in[6];
    const float* b2   = (const float*)d_in[7];
    const int* src = ei;
    const int* dst = ei + N_EDGES;
    float* out = (float*)d_out;

    void *p_agg1, *p_h, *p_xh, *p_th;
    cudaGetSymbolAddress(&p_agg1, g_agg1);
    cudaGetSymbolAddress(&p_h,    g_h);
    cudaGetSymbolAddress(&p_xh,   g_xh);
    cudaGetSymbolAddress(&p_th,   g_th);

    // K1: cvt + count   (g_cnt is zero: initial / restored by agg2<1>)
    k1_kernel<<<N_EDGES / 256, 256>>>(x, dst, (__half*)p_xh);
    // 3-kernel scan -> off/pos
    reduce_kernel<<<NB, SCAN_B>>>();
    scanblock_kernel<<<1, 256>>>();
    scatteroff_kernel<<<NB, SCAN_B>>>();
    // adjacency fill
    fill_kernel<<<(N_EDGES + 255) / 256, 256>>>(src, dst);
    // agg1 = mean(x_fp16)
    agg16_kernel<0><<<(N_NODES + 7) / 8, 256>>>((const __half*)p_xh, (float*)p_agg1);
    // GEMM layer 1: h = relu([agg1|x] @ W1 + b1)
    const int smem = SM_WORDS * (int)sizeof(uint32_t);   // 104960 B
    cudaFuncSetAttribute(mma_gemm_kernel<1>, cudaFuncAttributeMaxDynamicSharedMemorySize, smem);
    cudaFuncSetAttribute(mma_gemm_kernel<2>, cudaFuncAttributeMaxDynamicSharedMemorySize, smem);
    mma_gemm_kernel<1><<<GEMM_BLOCKS, 256, smem>>>((const float*)p_agg1, x,
                                                   W_l1, W_r1, b1,
                                                   (float*)p_h, (float*)nullptr,
                                                   (__half*)nullptr);
    // GEMM layer 2: t(fp16) + r2(fp32 -> out)
    mma_gemm_kernel<2><<<GEMM_BLOCKS, 256, smem>>>((const float*)p_h, (const float*)nullptr,
                                                   W_l2, W_r2, b2,
                                                   (float*)nullptr, out,
                                                   (__half*)p_th);
    // agg2 + sigmoid + cnt reset
    agg16_kernel<1><<<(N_NODES + 7) / 8, 256>>>((const __half*)p_th, out);
}

// round 17
// speedup vs baseline: 1.4938x; 1.4938x over previous
#include <cuda_runtime.h>
#include <cuda_fp16.h>
#include <math.h>
#include <stdint.h>

#define N_NODES 100000
#define N_EDGES 1600000
#define SCAN_B 512
#define NB ((N_NODES + SCAN_B - 1) / SCAN_B)   // 196
#define GEMM_BLOCKS ((N_NODES + 63) / 64)      // 1563

// ---------------- scratch (device globals; no allocation allowed) ----------
__device__ float  g_agg1[(size_t)N_NODES * 64];
__device__ float  g_h   [(size_t)N_NODES * 128];
__device__ __half g_xh  [(size_t)N_NODES * 64];   // fp16 copy of x
__device__ __half g_th  [(size_t)N_NODES * 64];   // fp16 t = h @ W_l2
__device__ int    g_cnt [N_NODES];
__device__ int    g_off [N_NODES];
__device__ int    g_pos [N_NODES];
__device__ int    g_adj [N_EDGES];
__device__ int    g_blocksum[NB];
__device__ int    g_blockoff[NB];

// ---------------- CSR construction ------------------------------------------
__global__ void count_kernel(const int* __restrict__ dst) {
    int i = blockIdx.x * blockDim.x + threadIdx.x;
    if (i < N_EDGES) atomicAdd(&g_cnt[dst[i]], 1);
}

__global__ void reduce_kernel() {
    __shared__ int s[SCAN_B / 32];
    int i = blockIdx.x * SCAN_B + threadIdx.x;
    int v = (i < N_NODES) ? g_cnt[i] : 0;
#pragma unroll
    for (int o = 16; o > 0; o >>= 1) v += __shfl_down_sync(0xffffffffu, v, o);
    if ((threadIdx.x & 31) == 0) s[threadIdx.x >> 5] = v;
    __syncthreads();
    if (threadIdx.x == 0) {
        int t = 0;
#pragma unroll
        for (int w = 0; w < SCAN_B / 32; w++) t += s[w];
        g_blocksum[blockIdx.x] = t;
    }
}

__global__ void scanblock_kernel() {
    __shared__ int s[256];
    int v = (threadIdx.x < NB) ? g_blocksum[threadIdx.x] : 0;
    s[threadIdx.x] = v;
    __syncthreads();
    for (int d = 1; d < 256; d <<= 1) {
        int t = (threadIdx.x >= d) ? s[threadIdx.x - d] : 0;
        __syncthreads();
        s[threadIdx.x] += t;
        __syncthreads();
    }
    if (threadIdx.x < NB)
        g_blockoff[threadIdx.x] = (threadIdx.x == 0) ? 0 : s[threadIdx.x - 1];
}

__global__ void scatteroff_kernel() {
    __shared__ int s[SCAN_B];
    int b = blockIdx.x;
    int i = b * SCAN_B + threadIdx.x;
    int v = (i < N_NODES) ? g_cnt[i] : 0;
    s[threadIdx.x] = v;
    __syncthreads();
    for (int d = 1; d < SCAN_B; d <<= 1) {
        int t = (threadIdx.x >= d) ? s[threadIdx.x - d] : 0;
        __syncthreads();
        s[threadIdx.x] += t;
        __syncthreads();
    }
    if (i < N_NODES) {
        int excl = s[threadIdx.x] - v + g_blockoff[b];
        g_off[i] = excl;
        g_pos[i] = excl;
    }
}

__global__ void fill_kernel(const int* __restrict__ src, const int* __restrict__ dst) {
    int e = blockIdx.x * blockDim.x + threadIdx.x;
    if (e < N_EDGES) {
        int d = dst[e];
        int p = atomicAdd(&g_pos[d], 1);
        g_adj[p] = src[e];
    }
}

// ---------------- x -> fp16 conversion ---------------------------------------
__global__ void cvt_kernel(const float* __restrict__ x, __half* __restrict__ xh) {
    int i = blockIdx.x * 256 + threadIdx.x;   // float4 index
    if (i >= N_NODES * 16) return;
    float4 v = __ldg((const float4*)x + i);
    __half2 h0 = __floats2half2_rn(v.x, v.y);
    __half2 h1 = __floats2half2_rn(v.z, v.w);
    ((__half2*)xh)[2 * i]     = h0;
    ((__half2*)xh)[2 * i + 1] = h1;
}

// ---------------- pull aggregation over fp16 features ------------------------
// One warp per node; 2 halves of 16 lanes, each half walks alternate neighbors
// with 4-deep pipelining. One neighbor row = 128 B = one cache line.
// FIN=1 fuses the layer-2 epilogue: out = sigmoid(mean + r2).
template <int FIN>
__global__ void __launch_bounds__(256)
agg16_kernel(const __half* __restrict__ feat, float* __restrict__ outp) {
    int node = blockIdx.x * 8 + (threadIdx.x >> 5);
    if (node >= N_NODES) return;
    int lane = threadIdx.x & 31;
    int half = lane >> 4;
    int q = lane & 15;
    int off = __ldg(&g_off[node]);
    int c = __ldg(&g_cnt[node]);
    const int* adj = g_adj + off;
    float4 acc = make_float4(0.f, 0.f, 0.f, 0.f);
    int i = half;
    for (; i + 6 < c; i += 8) {
        int s0 = __ldg(&adj[i]);
        int s1 = __ldg(&adj[i + 2]);
        int s2 = __ldg(&adj[i + 4]);
        int s3 = __ldg(&adj[i + 6]);
        uint2 r0 = __ldg((const uint2*)(feat + (size_t)s0 * 64) + q);
        uint2 r1 = __ldg((const uint2*)(feat + (size_t)s1 * 64) + q);
        uint2 r2 = __ldg((const uint2*)(feat + (size_t)s2 * 64) + q);
        uint2 r3 = __ldg((const uint2*)(feat + (size_t)s3 * 64) + q);
        float2 a0 = __half22float2(*(__half2*)&r0.x), b0 = __half22float2(*(__half2*)&r0.y);
        float2 a1 = __half22float2(*(__half2*)&r1.x), b1 = __half22float2(*(__half2*)&r1.y);
        float2 a2 = __half22float2(*(__half2*)&r2.x), b2 = __half22float2(*(__half2*)&r2.y);
        float2 a3 = __half22float2(*(__half2*)&r3.x), b3 = __half22float2(*(__half2*)&r3.y);
        acc.x += (a0.x + a1.x) + (a2.x + a3.x);
        acc.y += (a0.y + a1.y) + (a2.y + a3.y);
        acc.z += (b0.x + b1.x) + (b2.x + b3.x);
        acc.w += (b0.y + b1.y) + (b2.y + b3.y);
    }
    for (; i < c; i += 2) {
        int s0 = __ldg(&adj[i]);
        uint2 r0 = __ldg((const uint2*)(feat + (size_t)s0 * 64) + q);
        float2 a0 = __half22float2(*(__half2*)&r0.x), b0 = __half22float2(*(__half2*)&r0.y);
        acc.x += a0.x; acc.y += a0.y; acc.z += b0.x; acc.w += b0.y;
    }
    acc.x += __shfl_xor_sync(0xffffffffu, acc.x, 16);
    acc.y += __shfl_xor_sync(0xffffffffu, acc.y, 16);
    acc.z += __shfl_xor_sync(0xffffffffu, acc.z, 16);
    acc.w += __shfl_xor_sync(0xffffffffu, acc.w, 16);
    if (half == 0) {
        float sc = 1.0f / (float)max(c, 1);
        float4* dp = (float4*)(outp + (size_t)node * 64) + q;
        if (FIN) {
            float4 r = *dp;   // r2 written by gemm2
            float4 o;
            o.x = 1.0f / (1.0f + expf(-(acc.x * sc + r.x)));
            o.y = 1.0f / (1.0f + expf(-(acc.y * sc + r.y)));
            o.z = 1.0f / (1.0f + expf(-(acc.z * sc + r.z)));
            o.w = 1.0f / (1.0f + expf(-(acc.w * sc + r.w)));
            *dp = o;
        } else {
            *dp = make_float4(acc.x * sc, acc.y * sc, acc.z * sc, acc.w * sc);
        }
    }
}

// ---------------- bf16 split helpers ----------------------------------------
__device__ __forceinline__ uint32_t bf16hi_bits(float a) {
    uint32_t u = __float_as_uint(a);
    return (u + 0x7FFFu + ((u >> 16) & 1u)) & 0xFFFF0000u;  // RN-even to bf16
}
__device__ __forceinline__ void split_pack(float x0, float x1,
                                           uint32_t& hw, uint32_t& lw) {
    uint32_t r0 = bf16hi_bits(x0), r1 = bf16hi_bits(x1);
    hw = (r1 & 0xFFFF0000u) | (r0 >> 16);
    float l0 = x0 - __uint_as_float(r0);
    float l1 = x1 - __uint_as_float(r1);
    asm("cvt.rn.bf16x2.f32 %0, %1, %2;" : "=r"(lw) : "f"(l1), "f"(l0));
}

#define MMA_BF16(c, a0, a1, a2, a3, b0, b1) \
    asm volatile("mma.sync.aligned.m16n8k16.row.col.f32.bf16.bf16.f32 " \
        "{%0,%1,%2,%3}, {%4,%5,%6,%7}, {%8,%9}, {%0,%1,%2,%3};" \
        : "+f"((c)[0]), "+f"((c)[1]), "+f"((c)[2]), "+f"((c)[3]) \
        : "r"(a0), "r"(a1), "r"(a2), "r"(a3), "r"(b0), "r"(b1))

// ---------------- mma.sync bf16 3-term GEMM ----------------------------------
// Tile: 64 rows x 128 cols, K=128. 256 threads = 8 warps (4 row x 2 col groups).
// MODE 1: h = relu([agg1 | x] @ [W_l1 ; W_r1] + b1)  -> outA [row][128] fp32
// MODE 2: A=h; cols 0-63:  t = h@W_l2 -> outH[row][64] fp16;
//               cols 64-127: r2 = h@W_r2 + b2 -> outB[row][64] fp32
#define A_STR 68
#define W_STR 136
#define SM_AH 0
#define SM_AL (SM_AH + 64 * A_STR)
#define SM_WH (SM_AL + 64 * A_STR)
#define SM_WL (SM_WH + 64 * W_STR)
#define SM_BIAS (SM_WL + 64 * W_STR)
#define SM_WORDS (SM_BIAS + 128)              // 26240 words = 104960 B

template <int MODE>
__global__ void __launch_bounds__(256, 2)
mma_gemm_kernel(const float* __restrict__ A0, const float* __restrict__ A1,
                const float* __restrict__ Wa, const float* __restrict__ Wb,
                const float* __restrict__ bias,
                float* __restrict__ outA, float* __restrict__ outB,
                __half* __restrict__ outH) {
    extern __shared__ uint32_t smw[];
    float* sB = (float*)(smw + SM_BIAS);
    const int tid = threadIdx.x;
    const int base = blockIdx.x * 64;

    if (tid < 128)
        sB[tid] = (MODE == 1) ? __ldg(&bias[tid])
                              : (tid < 64 ? 0.0f : __ldg(&bias[tid - 64]));

    // ---- stage A: 64 rows x 64 k-pairs, split hi/lo ----
#pragma unroll
    for (int i = 0; i < 16; i++) {
        int idx = tid + 256 * i;
        int row = idx >> 6, k2 = idx & 63;
        int grow = base + row;
        float2 v = make_float2(0.f, 0.f);
        if (grow < N_NODES) {
            if (MODE == 1)
                v = (k2 < 32)
                    ? __ldg((const float2*)(A0 + (size_t)grow * 64) + k2)
                    : __ldg((const float2*)(A1 + (size_t)grow * 64) + (k2 - 32));
            else
                v = __ldg((const float2*)(A0 + (size_t)grow * 128) + k2);
        }
        uint32_t hw, lw;
        split_pack(v.x, v.y, hw, lw);
        smw[SM_AH + row * A_STR + k2] = hw;
        smw[SM_AL + row * A_STR + k2] = lw;
    }

    // ---- stage W: 64 k-pairs x 128 cols, split hi/lo ----
#pragma unroll
    for (int i = 0; i < 32; i++) {
        int idx = tid + 256 * i;
        int k2 = idx >> 7, n = idx & 127;
        int k = 2 * k2;
        float w0, w1;
        if (MODE == 1) {
            if (k < 64) { w0 = __ldg(&Wa[k * 128 + n]); w1 = __ldg(&Wa[(k + 1) * 128 + n]); }
            else        { w0 = __ldg(&Wb[(k - 64) * 128 + n]); w1 = __ldg(&Wb[(k - 63) * 128 + n]); }
        } else {
            if (n < 64) { w0 = __ldg(&Wa[k * 64 + n]); w1 = __ldg(&Wa[(k + 1) * 64 + n]); }
            else        { w0 = __ldg(&Wb[k * 64 + n - 64]); w1 = __ldg(&Wb[(k + 1) * 64 + n - 64]); }
        }
        uint32_t hw, lw;
        split_pack(w0, w1, hw, lw);
        smw[SM_WH + k2 * W_STR + n] = hw;
        smw[SM_WL + k2 * W_STR + n] = lw;
    }
    __syncthreads();

    // ---- mma compute ----
    const int lane = tid & 31;
    const int g = lane >> 2, q = lane & 3;
    const int wid = tid >> 5;
    const int Rbase = (wid & 3) * 16;
    const int Cw = (wid >> 2) * 64;
    const int rA0 = SM_AH + (Rbase + g) * A_STR;
    const int rA1 = SM_AH + (Rbase + g + 8) * A_STR;
    const int lA0 = SM_AL + (Rbase + g) * A_STR;
    const int lA1 = SM_AL + (Rbase + g + 8) * A_STR;

    float acc[8][4];
#pragma unroll
    for (int nt = 0; nt < 8; nt++)
#pragma unroll
        for (int p = 0; p < 4; p++) acc[nt][p] = 0.0f;

#pragma unroll
    for (int ks = 0; ks < 8; ks++) {
        int aw = ks * 8;
        uint32_t ah0 = smw[rA0 + aw + q],     ah1 = smw[rA1 + aw + q];
        uint32_t ah2 = smw[rA0 + aw + q + 4], ah3 = smw[rA1 + aw + q + 4];
        uint32_t al0 = smw[lA0 + aw + q],     al1 = smw[lA1 + aw + q];
        uint32_t al2 = smw[lA0 + aw + q + 4], al3 = smw[lA1 + aw + q + 4];
        int wr0 = (aw + q) * W_STR, wr1 = (aw + q + 4) * W_STR;
#pragma unroll
        for (int nt = 0; nt < 8; nt++) {
            int n = Cw + nt * 8 + g;
            uint32_t bh0 = smw[SM_WH + wr0 + n], bh1 = smw[SM_WH + wr1 + n];
            uint32_t bl0 = smw[SM_WL + wr0 + n], bl1 = smw[SM_WL + wr1 + n];
            MMA_BF16(acc[nt], ah0, ah1, ah2, ah3, bh0, bh1);
            MMA_BF16(acc[nt], al0, al1, al2, al3, bh0, bh1);
            MMA_BF16(acc[nt], ah0, ah1, ah2, ah3, bl0, bl1);
        }
    }

    // ---- epilogue ----
    const int r0 = base + Rbase + g;
    const int r1 = r0 + 8;
#pragma unroll
    for (int nt = 0; nt < 8; nt++) {
        int col = Cw + nt * 8 + 2 * q;
        float v00 = acc[nt][0] + sB[col], v01 = acc[nt][1] + sB[col + 1];
        float v10 = acc[nt][2] + sB[col], v11 = acc[nt][3] + sB[col + 1];
        if (MODE == 1) {
            v00 = fmaxf(v00, 0.f); v01 = fmaxf(v01, 0.f);
            v10 = fmaxf(v10, 0.f); v11 = fmaxf(v11, 0.f);
            if (r0 < N_NODES)
                *(float2*)(outA + (size_t)r0 * 128 + col) = make_float2(v00, v01);
            if (r1 < N_NODES)
                *(float2*)(outA + (size_t)r1 * 128 + col) = make_float2(v10, v11);
        } else {
            if (Cw == 0) {   // t -> fp16
                if (r0 < N_NODES)
                    *(__half2*)(outH + (size_t)r0 * 64 + col) = __floats2half2_rn(v00, v01);
                if (r1 < N_NODES)
                    *(__half2*)(outH + (size_t)r1 * 64 + col) = __floats2half2_rn(v10, v11);
            } else {         // r2 + b2 -> out (fp32)
                int cc = col - 64;
                if (r0 < N_NODES)
                    *(float2*)(outB + (size_t)r0 * 64 + cc) = make_float2(v00, v01);
                if (r1 < N_NODES)
                    *(float2*)(outB + (size_t)r1 * 64 + cc) = make_float2(v10, v11);
            }
        }
    }
}

// ---------------- launch ------------------------------------------------------
extern "C" void kernel_launch(void* const* d_in, const int* in_sizes, int n_in,
                              void* d_out, int out_size) {
    const float* x    = (const float*)d_in[0];
    const int*   ei   = (const int*)d_in[1];
    const float* W_l1 = (const float*)d_in[2];
    const float* W_r1 = (const float*)d_in[3];
    const float* b1   = (const float*)d_in[4];
    const float* W_l2 = (const float*)d_in[5];
    const float* W_r2 = (const float*)d_in[6];
    const float* b2   = (const float*)d_in[7];
    const int* src = ei;
    const int* dst = ei + N_EDGES;
    float* out = (float*)d_out;

    void *p_agg1, *p_cnt, *p_h, *p_xh, *p_th;
    cudaGetSymbolAddress(&p_agg1, g_agg1);
    cudaGetSymbolAddress(&p_cnt,  g_cnt);
    cudaGetSymbolAddress(&p_h,    g_h);
    cudaGetSymbolAddress(&p_xh,   g_xh);
    cudaGetSymbolAddress(&p_th,   g_th);

    // ---- x -> fp16, CSR build ----
    cudaMemsetAsync(p_cnt, 0, (size_t)N_NODES * sizeof(int));
    cvt_kernel<<<(N_NODES * 16 + 255) / 256, 256>>>(x, (__half*)p_xh);
    count_kernel<<<(N_EDGES + 255) / 256, 256>>>(dst);
    reduce_kernel<<<NB, SCAN_B>>>();
    scanblock_kernel<<<1, 256>>>();
    scatteroff_kernel<<<NB, SCAN_B>>>();
    fill_kernel<<<(N_EDGES + 255) / 256, 256>>>(src, dst);

    // ---- layer 1: agg1 = mean(x_fp16) ----
    agg16_kernel<0><<<(N_NODES + 7) / 8, 256>>>((const __half*)p_xh, (float*)p_agg1);

    const int smem = SM_WORDS * (int)sizeof(uint32_t);   // 104960 B
    cudaFuncSetAttribute(mma_gemm_kernel<1>, cudaFuncAttributeMaxDynamicSharedMemorySize, smem);
    cudaFuncSetAttribute(mma_gemm_kernel<2>, cudaFuncAttributeMaxDynamicSharedMemorySize, smem);

    mma_gemm_kernel<1><<<GEMM_BLOCKS, 256, smem>>>((const float*)p_agg1, x,
                                                   W_l1, W_r1, b1,
                                                   (float*)p_h, (float*)nullptr,
                                                   (__half*)nullptr);
    // ---- layer 2: t(fp16) + r2, then fused agg+sigmoid ----
    mma_gemm_kernel<2><<<GEMM_BLOCKS, 256, smem>>>((const float*)p_h, (const float*)nullptr,
                                                   W_l2, W_r2, b2,
                                                   (float*)nullptr, out,
                                                   (__half*)p_th);
    agg16_kernel<1><<<(N_NODES + 7) / 8, 256>>>((const __half*)p_th, out);
}